// round 15
// baseline (speedup 1.0000x reference)
#include <cuda_runtime.h>
#include <cuda_fp16.h>
#include <cstdint>

// ---------------- problem constants (fixed shapes) ----------------
#define NN     131072      // nodes
#define EE     2097152     // edges
#define GG     8192        // graphs
#define NPG    16
#define NSLOT  16384       // 2 per graph
#define GS     64
#define NOUT   200
#define NSLOTS_ZP 4        // partial slots for decode
#define ECAP   64          // per-slot edge bucket capacity
#define NUNITS 8192        // 64 M-blocks x 128 K-chunks

// ---------------- scratch (device globals; no runtime alloc) ----------------
__device__ int      d_mark[NN];
__device__ uint32_t d_bits[NN / 32];          // 16KB membership bitmask (L1-resident)
__device__ int      d_node_of[NSLOT];
__device__ int      d_cnt[NSLOT];
__device__ int      d_elist[NSLOT * ECAP];    // [slot][ECAP]
__device__ __half   d_Hh[NSLOT * GS];         // h per slot (fp16)
__device__ __half   d_Sh[GG * 128];           // fused ir features (fp16)
__device__ __half   d_W1h[208 * 16384];       // W1 transposed (n-major), fp16, zero-padded
__device__ float    d_Zp[(size_t)NSLOTS_ZP * GG * 208]; // decode partials (4 slots)

__device__ __forceinline__ uint32_t su32(const void* p) {
    return (uint32_t)__cvta_generic_to_shared(p);
}

// ---------------- stage 0: W1 transpose + fp16 round ----------------
__global__ void k_prep(const float* __restrict__ W1) {
    __shared__ float tile[32][33];
    int kb = blockIdx.x * 32, nb = blockIdx.y * 32;
    int tx = threadIdx.x, ty = threadIdx.y;
#pragma unroll
    for (int r = 0; r < 4; r++) {
        int k = kb + ty + r * 8;
        int n = nb + tx;
        tile[ty + r * 8][tx] = (n < NOUT) ? W1[(size_t)k * NOUT + n] : 0.f;
    }
    __syncthreads();
#pragma unroll
    for (int r = 0; r < 4; r++) {
        int n = nb + ty + r * 8;
        if (n < 208) d_W1h[(size_t)n * 16384 + kb + tx] = __float2half_rn(tile[tx][ty + r * 8]);
    }
}

// ---------------- stage A: mark / bucket-fill ----------------
__global__ void k_mark(const int* __restrict__ set_idx) {
    int s = blockIdx.x * blockDim.x + threadIdx.x;
    if (s >= NSLOT) return;
    int g = s >> 1, k = s & 1;
    int v = g * NPG + set_idx[g * 2 + k];
    d_node_of[s] = v;
    atomicMax(&d_mark[v], s);
    atomicOr(&d_bits[v >> 5], 1u << (v & 31));
}

// bucketed edge fill; 16 edges/thread; L1-resident bitmask pre-filter
__global__ void k_fill(const int* __restrict__ ei) {
    int e0 = (blockIdx.x * blockDim.x + threadIdx.x) * 16;
    if (e0 >= EE) return;
    int v[16];
#pragma unroll
    for (int b4 = 0; b4 < 4; b4++) {
        int4 a = *(const int4*)&ei[EE + e0 + b4 * 4];
        v[b4 * 4 + 0] = a.x; v[b4 * 4 + 1] = a.y;
        v[b4 * 4 + 2] = a.z; v[b4 * 4 + 3] = a.w;
    }
    uint32_t hit = 0;
#pragma unroll
    for (int q = 0; q < 16; q++)
        hit |= ((d_bits[v[q] >> 5] >> (v[q] & 31)) & 1u) << q;
    if (!hit) return;
#pragma unroll
    for (int q = 0; q < 16; q++) {
        if (hit & (1u << q)) {
            int r = d_mark[v[q]];
            int p = atomicAdd(&d_cnt[r], 1);
            if (p < ECAP) d_elist[r * ECAP + p] = ei[e0 + q];
        }
    }
}

// ---------------- fused stage A2+B: aggregate -> smem -> H GEMM -> fp16 -------
// Block: 128 slots. Phase 1: per-warp mean-aggregation into smem MXs[128][260]
// (stride 260 words: bank = 4*row+col, conflict-free for 8-row column reads).
// Phase 2: H = relu(MXs @ [Wl;Wr] + bl) straight out of smem.
#define MXS_STRIDE 260
#define FUSED_SMEM (128 * MXS_STRIDE * 4 + 16 * 64 * 4)   // 137216 B

__global__ void __launch_bounds__(256, 1)
k_agg_hgemm(const float* __restrict__ x, const float* __restrict__ Wl,
            const float* __restrict__ Wr, const float* __restrict__ bl) {
    extern __shared__ float fsm[];
    float* MXs = fsm;                         // [128][260]
    float (*Bs)[64] = (float (*)[64])(fsm + 128 * MXS_STRIDE);

    int tid = threadIdx.x;
    int lane = tid & 31, w = tid >> 5;
    int row0 = blockIdx.x * 128;
    const float4* x4 = (const float4*)x;

    // ---- phase 1: aggregation (each warp: 16 slots)
    for (int it = 0; it < 16; it++) {
        int sl = it * 8 + w;                  // local slot 0..127
        int s = row0 + sl;
        int v = d_node_of[s];
        int rep = d_mark[v];                  // bucket key (== s unless dup)
        const int* el = &d_elist[rep * ECAP];
        int deg = d_cnt[rep];
        int n = deg > ECAP ? ECAP : deg;
        float4 acc = make_float4(0.f, 0.f, 0.f, 0.f);
        int i = 0;
        for (; i + 4 <= n; i += 4) {
            int s0 = el[i], s1 = el[i + 1], s2 = el[i + 2], s3 = el[i + 3];
            float4 t0 = x4[(size_t)s0 * 32 + lane];
            float4 t1 = x4[(size_t)s1 * 32 + lane];
            float4 t2 = x4[(size_t)s2 * 32 + lane];
            float4 t3 = x4[(size_t)s3 * 32 + lane];
            acc.x += (t0.x + t1.x) + (t2.x + t3.x);
            acc.y += (t0.y + t1.y) + (t2.y + t3.y);
            acc.z += (t0.z + t1.z) + (t2.z + t3.z);
            acc.w += (t0.w + t1.w) + (t2.w + t3.w);
        }
        for (; i < n; i++) {
            float4 t = x4[(size_t)el[i] * 32 + lane];
            acc.x += t.x; acc.y += t.y; acc.z += t.z; acc.w += t.w;
        }
        float inv = 1.f / (float)(deg > 0 ? deg : 1);
        acc.x *= inv; acc.y *= inv; acc.z *= inv; acc.w *= inv;
        float* row = MXs + sl * MXS_STRIDE;
        *(float4*)(row + lane * 4) = acc;
        *(float4*)(row + 128 + lane * 4) = x4[(size_t)v * 32 + lane];
    }
    __syncthreads();

    // ---- phase 2: GEMM from smem
    int tx = tid & 15, ty = tid >> 4;
    float acc[8][4];
#pragma unroll
    for (int i = 0; i < 8; i++)
#pragma unroll
        for (int j = 0; j < 4; j++) acc[i][j] = 0.f;

    for (int kb = 0; kb < 256; kb += 16) {
        {
            int k = tid >> 4, o4 = (tid & 15) * 4;
            int kg = kb + k;
            const float* Wsrc = (kg < 128) ? &Wl[kg * 64 + o4] : &Wr[(kg - 128) * 64 + o4];
            *(float4*)&Bs[k][o4] = *(const float4*)Wsrc;
        }
        __syncthreads();
#pragma unroll
        for (int k = 0; k < 16; k++) {
            float a[8], b[4];
#pragma unroll
            for (int i = 0; i < 8; i++) a[i] = MXs[(ty * 8 + i) * MXS_STRIDE + kb + k];
#pragma unroll
            for (int j = 0; j < 4; j++) b[j] = Bs[k][tx * 4 + j];
#pragma unroll
            for (int i = 0; i < 8; i++)
#pragma unroll
                for (int j = 0; j < 4; j++) acc[i][j] += a[i] * b[j];
        }
        __syncthreads();
    }
#pragma unroll
    for (int i = 0; i < 8; i++)
#pragma unroll
        for (int j = 0; j < 4; j++) {
            int o = tx * 4 + j;
            d_Hh[(size_t)(row0 + ty * 8 + i) * 64 + o] =
                __float2half_rn(fmaxf(acc[i][j] + bl[o], 0.f));
        }
}

// ---------------- stage C: S = relu(ir @ Wir + bir) -> fp16 ----------------
__global__ void k_sgemm(const float* __restrict__ ir, const float* __restrict__ Wir,
                        const float* __restrict__ bir) {
    __shared__ float irs[64][32];
    __shared__ float Ws[32][128];
    int tid = threadIdx.x;
    int g0 = blockIdx.x * 64;
    for (int l = tid; l < 64 * 32; l += 256) irs[l >> 5][l & 31] = ir[(size_t)g0 * 32 + l];
    for (int l = tid; l < 32 * 128; l += 256) Ws[l >> 7][l & 127] = Wir[l];
    __syncthreads();
    int o = tid & 127, h = tid >> 7;
    float bo = bir[o];
    for (int gg = h; gg < 64; gg += 2) {
        float acc = bo;
#pragma unroll
        for (int k = 0; k < 32; k++) acc += irs[gg][k] * Ws[k][o];
        d_Sh[(size_t)(g0 + gg) * 128 + o] = __float2half_rn(fmaxf(acc, 0.f));
    }
}

// ---------------- stage D: persistent decode GEMM, 2 CTAs/SM, k64 stages ------
// Z[8192,200] = A[8192,16384] @ W1, A[g, i*128+j] = P[g,i]*S[g,j].
// Grid = 2*NSM. CTA c: h = c&1 selects N-half, c2 = c>>1 selects unit range.
// Stage = k64 (four k16 sub-steps per sync), 3-deep cp.async ring.
#define NSTB 3
#define BROW 144                       // 128B data + 16B pad (bank = 4*gq+l4, distinct)
#define BSTG (104 * BROW)              // 14976 B per stage
#define SM_B 0
#define SM_S (NSTB * BSTG)             // 44928; S: 128 rows x 272B = 34816
#define SM_P (SM_S + 128 * 272)        // 79744; P: 128 rows x 264B = 33792
#define SM_TOTAL (SM_P + 128 * 264)    // 113536

__global__ void __launch_bounds__(256, 2)
k_decode() {
    extern __shared__ char smem[];
    uint32_t sb = su32(smem);
    int tid = threadIdx.x;
    int lane = tid & 31, warp = tid >> 5;
    int wm = warp & 3, wn = warp >> 2;
    int gq = lane >> 2, l4 = lane & 3;
    int m_base = wm * 32;
    int c = blockIdx.x;
    int h = c & 1, c2 = c >> 1, NC2 = gridDim.x >> 1;
    int u0 = (c2 * NUNITS) / NC2;
    int u1 = ((c2 + 1) * NUNITS) / NC2;
    int T = (u1 - u0) * 2;             // k64 stages (2 per K-chunk of 128)
    int m = u0 >> 7;

    // ---- tile loaders
    auto load_tiles = [&](int mb) {
        int g0 = mb * 128;
        for (int l = tid; l < 2048; l += 256) {
            int row = l >> 4, cc = l & 15;
            *(float4*)(smem + SM_S + row * 272 + cc * 16) =
                *(const float4*)((const char*)d_Sh + (size_t)(g0 + row) * 256 + cc * 16);
        }
        for (int l = tid; l < 4096; l += 256) {
            int row = l >> 5, grp = l & 31;
            *(float2*)(smem + SM_P + row * 264 + grp * 8) =
                *(const float2*)((const char*)d_Hh +
                    ((size_t)(2 * (g0 + row) + (grp >> 4)) * 64 + (grp & 15) * 4) * 2);
        }
    };
    // ---- B stage loader (cp.async): 104 rows x 128B (k64)
    auto load_stage = [&](int buf, int t) {
        int iu = (u0 + (t >> 1)) & 127;
        int kb = iu * 128 + (t & 1) * 64;
        for (int l = tid; l < 832; l += 256) {
            int row = l >> 3, q = l & 7;
            uint32_t dst = sb + SM_B + buf * BSTG + row * BROW + q * 16;
            const char* src = (const char*)(d_W1h + (size_t)(h * 104 + row) * 16384 + kb + q * 8);
            asm volatile("cp.async.cg.shared.global [%0], [%1], 16;\n"
                         :: "r"(dst), "l"(src));
        }
        asm volatile("cp.async.commit_group;\n");
    };

    float acc[2][7][4];
#pragma unroll
    for (int a = 0; a < 2; a++)
#pragma unroll
        for (int b = 0; b < 7; b++)
#pragma unroll
            for (int q = 0; q < 4; q++) acc[a][b][q] = 0.f;

    auto flush = [&](int mb) {
        int slot = c2 & 3;
        int base_col = h * 104;
#pragma unroll
        for (int mt = 0; mt < 2; mt++) {
            int gr = mb * 128 + m_base + mt * 16 + gq;
            size_t b0 = ((size_t)slot * GG + gr) * 208;
            size_t b1 = ((size_t)slot * GG + gr + 8) * 208;
            if (wn == 0) {
#pragma unroll
                for (int j = 0; j < 7; j++) {
                    int c0 = base_col + j * 8 + 2 * l4;
                    *(float2*)&d_Zp[b0 + c0] = make_float2(acc[mt][j][0], acc[mt][j][1]);
                    *(float2*)&d_Zp[b1 + c0] = make_float2(acc[mt][j][2], acc[mt][j][3]);
                }
            } else {
#pragma unroll
                for (int j = 0; j < 5; j++) {
                    int c0 = base_col + 56 + j * 8 + 2 * l4;
                    *(float2*)&d_Zp[b0 + c0] = make_float2(acc[mt][j][0], acc[mt][j][1]);
                    *(float2*)&d_Zp[b1 + c0] = make_float2(acc[mt][j][2], acc[mt][j][3]);
                }
                if (h == 0) {
                    int c0 = 96 + 2 * l4;
                    *(float2*)&d_Zp[b0 + c0] = make_float2(acc[mt][5][0], acc[mt][5][1]);
                    *(float2*)&d_Zp[b1 + c0] = make_float2(acc[mt][5][2], acc[mt][5][3]);
                }
            }
        }
#pragma unroll
        for (int a = 0; a < 2; a++)
#pragma unroll
            for (int b = 0; b < 7; b++)
#pragma unroll
                for (int q = 0; q < 4; q++) acc[a][b][q] = 0.f;
    };

    load_tiles(m);
    __syncthreads();
    load_stage(0, 0); load_stage(1, 1);

    __half2 pb[4];
    const int s_cb = (2 * l4) * 2;       // byte offset of j0 within S row

    for (int t = 0; t < T; t++) {
        int u = u0 + (t >> 1);
        int mblk = u >> 7;
        if (mblk != m) {
            flush(m);
            __syncthreads();
            load_tiles(mblk);
            __syncthreads();
            m = mblk;
        }
        asm volatile("cp.async.wait_group 1;\n" ::: "memory");
        __syncthreads();
        if (t + 2 < T) load_stage((t + 2) % NSTB, t + 2);
        else asm volatile("cp.async.commit_group;\n");

        if ((t & 1) == 0) {
            int iu = u & 127;
#pragma unroll
            for (int t4 = 0; t4 < 4; t4++) {
                __half ph = *(const __half*)(smem + SM_P + (m_base + gq + 8 * t4) * 264 + iu * 2);
                pb[t4] = __half2half2(ph);
            }
        }
        const char* bst = smem + SM_B + (t % NSTB) * BSTG;

#pragma unroll
        for (int ss = 0; ss < 4; ss++) {
            int jb = (t & 1) * 64 + ss * 16;
            // A fragments (K-only -> same for both N-halves)
            uint32_t afr[2][4];
#pragma unroll
            for (int mt = 0; mt < 2; mt++) {
                const char* r0p = smem + SM_S + (m_base + mt * 16 + gq) * 272 + jb * 2 + s_cb;
                const char* r1p = r0p + 8 * 272;
                __half2 s00 = *(const __half2*)(r0p);
                __half2 s10 = *(const __half2*)(r1p);
                __half2 s01 = *(const __half2*)(r0p + 16);
                __half2 s11 = *(const __half2*)(r1p + 16);
                __half2 a0 = __hmul2(pb[mt * 2],     s00);
                __half2 a1 = __hmul2(pb[mt * 2 + 1], s10);
                __half2 a2 = __hmul2(pb[mt * 2],     s01);
                __half2 a3 = __hmul2(pb[mt * 2 + 1], s11);
                afr[mt][0] = *(uint32_t*)&a0; afr[mt][1] = *(uint32_t*)&a1;
                afr[mt][2] = *(uint32_t*)&a2; afr[mt][3] = *(uint32_t*)&a3;
            }

#define MMA_TILE(jj, tl)                                                        \
            {                                                                   \
                const char* brow = bst + ((tl) * 8 + gq) * BROW + ss * 32 + l4 * 4; \
                uint32_t b0 = *(const uint32_t*)(brow);                         \
                uint32_t b1 = *(const uint32_t*)(brow + 16);                    \
                _Pragma("unroll")                                               \
                for (int mt = 0; mt < 2; mt++) {                                \
                    asm volatile(                                               \
                        "mma.sync.aligned.m16n8k16.row.col.f32.f16.f16.f32 "    \
                        "{%0,%1,%2,%3}, {%4,%5,%6,%7}, {%8,%9}, {%0,%1,%2,%3};" \
                        : "+f"(acc[mt][jj][0]), "+f"(acc[mt][jj][1]),           \
                          "+f"(acc[mt][jj][2]), "+f"(acc[mt][jj][3])            \
                        : "r"(afr[mt][0]), "r"(afr[mt][1]),                     \
                          "r"(afr[mt][2]), "r"(afr[mt][3]),                     \
                          "r"(b0), "r"(b1));                                    \
                }                                                               \
            }

            if (wn == 0) {
#pragma unroll
                for (int j = 0; j < 7; j++) MMA_TILE(j, j)
            } else {
#pragma unroll
                for (int j = 0; j < 5; j++) MMA_TILE(j, 7 + j)
                if (h == 0) MMA_TILE(5, 12)
            }
#undef MMA_TILE
        }
    }

    flush(m);
}

// ---------------- epilogue: sum 4 partial slots, bias+relu, @W2 ----------------
__global__ void k_final(const float* __restrict__ b1, const float* __restrict__ W2,
                        const float* __restrict__ b2, float* __restrict__ out) {
    int g = (blockIdx.x * blockDim.x + threadIdx.x) >> 5;
    int lane = threadIdx.x & 31;
    if (g >= GG) return;
    float a0 = 0.f, a1 = 0.f;
    for (int n = lane; n < NOUT; n += 32) {
        float v = b1[n];
#pragma unroll
        for (int zz = 0; zz < NSLOTS_ZP; zz++) v += d_Zp[((size_t)zz * GG + g) * 208 + n];
        v = fmaxf(v, 0.f);
        a0 += v * W2[n * 2];
        a1 += v * W2[n * 2 + 1];
    }
#pragma unroll
    for (int o = 16; o; o >>= 1) {
        a0 += __shfl_down_sync(0xffffffffu, a0, o);
        a1 += __shfl_down_sync(0xffffffffu, a1, o);
    }
    if (lane == 0) { out[g * 2] = a0 + b2[0]; out[g * 2 + 1] = a1 + b2[1]; }
}

// ---------------- host ----------------
extern "C" void kernel_launch(void* const* d_in, const int* in_sizes, int n_in,
                              void* d_out, int out_size) {
    const float* x       = (const float*)d_in[0];
    const int*   ei      = (const int*)d_in[1];
    const int*   set_idx = (const int*)d_in[2];
    const float* ir      = (const float*)d_in[4];
    const float* Wl      = (const float*)d_in[5];
    const float* bl      = (const float*)d_in[6];
    const float* Wr      = (const float*)d_in[7];
    const float* Wir     = (const float*)d_in[8];
    const float* bir     = (const float*)d_in[9];
    const float* W1      = (const float*)d_in[10];
    const float* b1      = (const float*)d_in[11];
    const float* W2      = (const float*)d_in[12];
    const float* b2      = (const float*)d_in[13];
    float* out = (float*)d_out;

    // one-time host-side setup (streams/events are host resources, no dev mem)
    static cudaStream_t s1 = nullptr, s2 = nullptr;
    static cudaEvent_t ef = nullptr, e1 = nullptr, e2 = nullptr;
    static int nsm = 0;
    if (!s1) {
        cudaStreamCreateWithFlags(&s1, cudaStreamNonBlocking);
        cudaStreamCreateWithFlags(&s2, cudaStreamNonBlocking);
        cudaEventCreateWithFlags(&ef, cudaEventDisableTiming);
        cudaEventCreateWithFlags(&e1, cudaEventDisableTiming);
        cudaEventCreateWithFlags(&e2, cudaEventDisableTiming);
        cudaFuncSetAttribute(k_decode, cudaFuncAttributeMaxDynamicSharedMemorySize, SM_TOTAL);
        cudaFuncSetAttribute(k_agg_hgemm, cudaFuncAttributeMaxDynamicSharedMemorySize, FUSED_SMEM);
        cudaDeviceGetAttribute(&nsm, cudaDevAttrMultiProcessorCount, 0);
        if (nsm < 4) nsm = 4;
    }

    void *p_mark, *p_cnt, *p_zp, *p_bits;
    cudaGetSymbolAddress(&p_mark, d_mark);
    cudaGetSymbolAddress(&p_cnt,  d_cnt);
    cudaGetSymbolAddress(&p_zp,   d_Zp);
    cudaGetSymbolAddress(&p_bits, d_bits);
    cudaMemsetAsync(p_mark, 0xFF, (size_t)NN * 4, 0);
    cudaMemsetAsync(p_bits, 0,    (size_t)(NN / 32) * 4, 0);
    cudaMemsetAsync(p_cnt,  0,    (size_t)NSLOT * 4, 0);

    // fork: independent stages on side streams
    cudaEventRecord(ef, 0);
    cudaStreamWaitEvent(s1, ef, 0);
    cudaStreamWaitEvent(s2, ef, 0);
    cudaMemsetAsync(p_zp, 0, (size_t)NSLOTS_ZP * GG * 208 * 4, s1);
    k_prep<<<dim3(512, 7), dim3(32, 8), 0, s1>>>(W1);
    k_sgemm<<<GG / 64, 256, 0, s2>>>(ir, Wir, bir);

    // main chain on origin stream
    k_mark<<<NSLOT / 256, 256>>>(set_idx);
    k_fill<<<EE / 4096, 256>>>(ei);
    k_agg_hgemm<<<NSLOT / 128, 256, FUSED_SMEM>>>(x, Wl, Wr, bl);

    // join
    cudaEventRecord(e1, s1);
    cudaEventRecord(e2, s2);
    cudaStreamWaitEvent(0, e1, 0);
    cudaStreamWaitEvent(0, e2, 0);

    k_decode<<<2 * nsm, 256, SM_TOTAL>>>();
    k_final<<<(GG * 32 + 255) / 256, 256>>>(b1, W2, b2, out);
}

// round 16
// speedup vs baseline: 1.1270x; 1.1270x over previous
#include <cuda_runtime.h>
#include <cuda_fp16.h>
#include <cstdint>

// ---------------- problem constants (fixed shapes) ----------------
#define NN     131072      // nodes
#define EE     2097152     // edges
#define GG     8192        // graphs
#define NPG    16
#define NSLOT  16384       // 2 per graph
#define GS     64
#define NOUT   200
#define NSLOTS_ZP 4        // partial slots for decode
#define ECAP   64          // per-slot edge bucket capacity
#define NUNITS 8192        // 64 M-blocks x 128 K-chunks

// ---------------- scratch (device globals; no runtime alloc) ----------------
// d_meta = [mark(NN) | bits(NN/32) | cnt(NSLOT)], single zero-memset.
// mark encoding: 0 = unmarked, slot+1 = marked.
__device__ int      d_meta[NN + NN / 32 + NSLOT];
#define D_MARK (d_meta)
#define D_BITS ((uint32_t*)(d_meta + NN))
#define D_CNT  (d_meta + NN + NN / 32)

__device__ int      d_node_of[NSLOT];
__device__ int      d_elist[NSLOT * ECAP];    // [slot][ECAP]
__device__ float    d_MX[NSLOT * 256];        // [slot][mean(128) | xv(128)]
__device__ __half   d_Hh[NSLOT * GS];         // h per slot (fp16)
__device__ __half   d_Sh[GG * 128];           // fused ir features (fp16)
__device__ __half   d_W1h[208 * 16384];       // W1 transposed (n-major), fp16, zero-padded
__device__ float    d_Zp[(size_t)NSLOTS_ZP * GG * 208]; // decode partials (4 slots)

__device__ __forceinline__ uint32_t su32(const void* p) {
    return (uint32_t)__cvta_generic_to_shared(p);
}

// ---------------- stage 0: W1 transpose + fp16 round ----------------
__global__ void k_prep(const float* __restrict__ W1) {
    __shared__ float tile[32][33];
    int kb = blockIdx.x * 32, nb = blockIdx.y * 32;
    int tx = threadIdx.x, ty = threadIdx.y;
#pragma unroll
    for (int r = 0; r < 4; r++) {
        int k = kb + ty + r * 8;
        int n = nb + tx;
        tile[ty + r * 8][tx] = (n < NOUT) ? W1[(size_t)k * NOUT + n] : 0.f;
    }
    __syncthreads();
#pragma unroll
    for (int r = 0; r < 4; r++) {
        int n = nb + ty + r * 8;
        if (n < 208) d_W1h[(size_t)n * 16384 + kb + tx] = __float2half_rn(tile[tx][ty + r * 8]);
    }
}

// ---------------- stage A: mark / bucket-fill / aggregate ----------------
__global__ void k_mark(const int* __restrict__ set_idx) {
    int s = blockIdx.x * blockDim.x + threadIdx.x;
    if (s >= NSLOT) return;
    int g = s >> 1, k = s & 1;
    int v = g * NPG + set_idx[g * 2 + k];
    d_node_of[s] = v;
    atomicMax(&D_MARK[v], s + 1);
    atomicOr(&D_BITS[v >> 5], 1u << (v & 31));
}

// bucketed edge fill; 8 edges/thread; L1-resident bitmask pre-filter
__global__ void k_fill(const int* __restrict__ ei) {
    int e0 = (blockIdx.x * blockDim.x + threadIdx.x) * 8;
    if (e0 >= EE) return;
    int4 a = *(const int4*)&ei[EE + e0];
    int4 b = *(const int4*)&ei[EE + e0 + 4];
    int v[8] = {a.x, a.y, a.z, a.w, b.x, b.y, b.z, b.w};
    uint32_t hit = 0;
#pragma unroll
    for (int q = 0; q < 8; q++)
        hit |= ((D_BITS[v[q] >> 5] >> (v[q] & 31)) & 1u) << q;
    if (!hit) return;
#pragma unroll
    for (int q = 0; q < 8; q++) {
        if (hit & (1u << q)) {
            int r = D_MARK[v[q]] - 1;
            int p = atomicAdd(&D_CNT[r], 1);
            if (p < ECAP) d_elist[r * ECAP + p] = ei[e0 + q];
        }
    }
}

// aggregate: every slot reads its representative's bucket (no fix pass needed)
__global__ void k_agg(const float* __restrict__ x) {
    int s = blockIdx.x * 8 + (threadIdx.x >> 5);
    int lane = threadIdx.x & 31;
    int v = d_node_of[s];
    int rep = D_MARK[v] - 1;                     // bucket key (== s unless dup)
    const float4* x4 = (const float4*)x;
    const int* el = &d_elist[rep * ECAP];
    int deg = D_CNT[rep];
    int n = deg > ECAP ? ECAP : deg;
    float4 acc = make_float4(0.f, 0.f, 0.f, 0.f);
    int i = 0;
    for (; i + 4 <= n; i += 4) {
        int s0 = el[i], s1 = el[i + 1], s2 = el[i + 2], s3 = el[i + 3];
        float4 t0 = x4[(size_t)s0 * 32 + lane];
        float4 t1 = x4[(size_t)s1 * 32 + lane];
        float4 t2 = x4[(size_t)s2 * 32 + lane];
        float4 t3 = x4[(size_t)s3 * 32 + lane];
        acc.x += (t0.x + t1.x) + (t2.x + t3.x);
        acc.y += (t0.y + t1.y) + (t2.y + t3.y);
        acc.z += (t0.z + t1.z) + (t2.z + t3.z);
        acc.w += (t0.w + t1.w) + (t2.w + t3.w);
    }
    for (; i < n; i++) {
        float4 t = x4[(size_t)el[i] * 32 + lane];
        acc.x += t.x; acc.y += t.y; acc.z += t.z; acc.w += t.w;
    }
    float inv = 1.f / (float)(deg > 0 ? deg : 1);
    acc.x *= inv; acc.y *= inv; acc.z *= inv; acc.w *= inv;
    float4* MX4 = (float4*)d_MX;
    MX4[(size_t)s * 64 + lane]      = acc;
    MX4[(size_t)s * 64 + 32 + lane] = x4[(size_t)v * 32 + lane];
}

// ---------------- stage B: H = relu(MX @ [Wl;Wr] + bl) -> fp16 ----------------
__global__ void k_hgemm(const float* __restrict__ Wl, const float* __restrict__ Wr,
                        const float* __restrict__ bl) {
    __shared__ float As[16][132];   // [k][row], transposed
    __shared__ float Bs[16][64];
    int tid = threadIdx.x;
    int tx = tid & 15, ty = tid >> 4;
    int row0 = blockIdx.x * 128;
    float acc[8][4];
#pragma unroll
    for (int i = 0; i < 8; i++)
#pragma unroll
        for (int j = 0; j < 4; j++) acc[i][j] = 0.f;

    for (int kb = 0; kb < 256; kb += 16) {
        for (int l = tid; l < 512; l += 256) {
            int r = l >> 2, q = l & 3;
            float4 v = *(const float4*)&d_MX[(size_t)(row0 + r) * 256 + kb + q * 4];
            As[q * 4 + 0][r] = v.x; As[q * 4 + 1][r] = v.y;
            As[q * 4 + 2][r] = v.z; As[q * 4 + 3][r] = v.w;
        }
        {
            int k = tid >> 4, o4 = (tid & 15) * 4;
            int kg = kb + k;
            const float* Wsrc = (kg < 128) ? &Wl[kg * 64 + o4] : &Wr[(kg - 128) * 64 + o4];
            *(float4*)&Bs[k][o4] = *(const float4*)Wsrc;
        }
        __syncthreads();
#pragma unroll
        for (int k = 0; k < 16; k++) {
            float a[8], b[4];
#pragma unroll
            for (int i = 0; i < 8; i++) a[i] = As[k][ty * 8 + i];
#pragma unroll
            for (int j = 0; j < 4; j++) b[j] = Bs[k][tx * 4 + j];
#pragma unroll
            for (int i = 0; i < 8; i++)
#pragma unroll
                for (int j = 0; j < 4; j++) acc[i][j] += a[i] * b[j];
        }
        __syncthreads();
    }
#pragma unroll
    for (int i = 0; i < 8; i++)
#pragma unroll
        for (int j = 0; j < 4; j++) {
            int o = tx * 4 + j;
            d_Hh[(size_t)(row0 + ty * 8 + i) * 64 + o] =
                __float2half_rn(fmaxf(acc[i][j] + bl[o], 0.f));
        }
}

// ---------------- stage C: S = relu(ir @ Wir + bir) -> fp16 ----------------
__global__ void k_sgemm(const float* __restrict__ ir, const float* __restrict__ Wir,
                        const float* __restrict__ bir) {
    __shared__ float irs[64][32];
    __shared__ float Ws[32][128];
    int tid = threadIdx.x;
    int g0 = blockIdx.x * 64;
    for (int l = tid; l < 64 * 32; l += 256) irs[l >> 5][l & 31] = ir[(size_t)g0 * 32 + l];
    for (int l = tid; l < 32 * 128; l += 256) Ws[l >> 7][l & 127] = Wir[l];
    __syncthreads();
    int o = tid & 127, h = tid >> 7;
    float bo = bir[o];
    for (int gg = h; gg < 64; gg += 2) {
        float acc = bo;
#pragma unroll
        for (int k = 0; k < 32; k++) acc += irs[gg][k] * Ws[k][o];
        d_Sh[(size_t)(g0 + gg) * 128 + o] = __float2half_rn(fmaxf(acc, 0.f));
    }
}

// ---------------- stage D: persistent decode GEMM, 2 CTAs/SM, k64 stages ------
// Z[8192,200] = A[8192,16384] @ W1, A[g, i*128+j] = P[g,i]*S[g,j].
// Grid = 2*NSM. CTA c: h = c&1 selects N-half, c2 = c>>1 selects unit range.
// Stage = k64 (four k16 sub-steps per sync), 3-deep cp.async ring.
// B tiles depend only on k-index (not M-block) -> prefetch valid across M switch.
#define NSTB 3
#define BROW 144                       // 128B data + 16B pad (bank = 4*gq+l4, distinct)
#define BSTG (104 * BROW)              // 14976 B per stage
#define SM_B 0
#define SM_S (NSTB * BSTG)             // 44928; S: 128 rows x 272B = 34816
#define SM_P (SM_S + 128 * 272)        // 79744; P: 128 rows x 264B = 33792
#define SM_TOTAL (SM_P + 128 * 264)    // 113536

__global__ void __launch_bounds__(256, 2)
k_decode() {
    extern __shared__ char smem[];
    uint32_t sb = su32(smem);
    int tid = threadIdx.x;
    int lane = tid & 31, warp = tid >> 5;
    int wm = warp & 3, wn = warp >> 2;
    int gq = lane >> 2, l4 = lane & 3;
    int m_base = wm * 32;
    int c = blockIdx.x;
    int h = c & 1, c2 = c >> 1, NC2 = gridDim.x >> 1;
    int u0 = (c2 * NUNITS) / NC2;
    int u1 = ((c2 + 1) * NUNITS) / NC2;
    int T = (u1 - u0) * 2;             // k64 stages (2 per K-chunk of 128)
    int m = u0 >> 7;

    // ---- tile loaders
    auto load_tiles = [&](int mb) {
        int g0 = mb * 128;
        for (int l = tid; l < 2048; l += 256) {
            int row = l >> 4, cc = l & 15;
            *(float4*)(smem + SM_S + row * 272 + cc * 16) =
                *(const float4*)((const char*)d_Sh + (size_t)(g0 + row) * 256 + cc * 16);
        }
        for (int l = tid; l < 4096; l += 256) {
            int row = l >> 5, grp = l & 31;
            *(float2*)(smem + SM_P + row * 264 + grp * 8) =
                *(const float2*)((const char*)d_Hh +
                    ((size_t)(2 * (g0 + row) + (grp >> 4)) * 64 + (grp & 15) * 4) * 2);
        }
    };
    // ---- B stage loader (cp.async): 104 rows x 128B (k64)
    auto load_stage = [&](int buf, int t) {
        int iu = (u0 + (t >> 1)) & 127;
        int kb = iu * 128 + (t & 1) * 64;
        for (int l = tid; l < 832; l += 256) {
            int row = l >> 3, q = l & 7;
            uint32_t dst = sb + SM_B + buf * BSTG + row * BROW + q * 16;
            const char* src = (const char*)(d_W1h + (size_t)(h * 104 + row) * 16384 + kb + q * 8);
            asm volatile("cp.async.cg.shared.global [%0], [%1], 16;\n"
                         :: "r"(dst), "l"(src));
        }
        asm volatile("cp.async.commit_group;\n");
    };

    float acc[2][7][4];
#pragma unroll
    for (int a = 0; a < 2; a++)
#pragma unroll
        for (int b = 0; b < 7; b++)
#pragma unroll
            for (int q = 0; q < 4; q++) acc[a][b][q] = 0.f;

    auto flush = [&](int mb) {
        int slot = c2 & 3;
        int base_col = h * 104;
#pragma unroll
        for (int mt = 0; mt < 2; mt++) {
            int gr = mb * 128 + m_base + mt * 16 + gq;
            size_t b0 = ((size_t)slot * GG + gr) * 208;
            size_t b1 = ((size_t)slot * GG + gr + 8) * 208;
            if (wn == 0) {
#pragma unroll
                for (int j = 0; j < 7; j++) {
                    int c0 = base_col + j * 8 + 2 * l4;
                    *(float2*)&d_Zp[b0 + c0] = make_float2(acc[mt][j][0], acc[mt][j][1]);
                    *(float2*)&d_Zp[b1 + c0] = make_float2(acc[mt][j][2], acc[mt][j][3]);
                }
            } else {
#pragma unroll
                for (int j = 0; j < 5; j++) {
                    int c0 = base_col + 56 + j * 8 + 2 * l4;
                    *(float2*)&d_Zp[b0 + c0] = make_float2(acc[mt][j][0], acc[mt][j][1]);
                    *(float2*)&d_Zp[b1 + c0] = make_float2(acc[mt][j][2], acc[mt][j][3]);
                }
                if (h == 0) {
                    int c0 = 96 + 2 * l4;
                    *(float2*)&d_Zp[b0 + c0] = make_float2(acc[mt][5][0], acc[mt][5][1]);
                    *(float2*)&d_Zp[b1 + c0] = make_float2(acc[mt][5][2], acc[mt][5][3]);
                }
            }
        }
#pragma unroll
        for (int a = 0; a < 2; a++)
#pragma unroll
            for (int b = 0; b < 7; b++)
#pragma unroll
                for (int q = 0; q < 4; q++) acc[a][b][q] = 0.f;
    };

    load_tiles(m);
    __syncthreads();
    load_stage(0, 0); load_stage(1, 1);

    __half2 pb[4];
    const int s_cb = (2 * l4) * 2;       // byte offset of j0 within S row

    for (int t = 0; t < T; t++) {
        int u = u0 + (t >> 1);
        int mblk = u >> 7;
        if (mblk != m) {
            flush(m);
            __syncthreads();
            load_tiles(mblk);
            __syncthreads();
            m = mblk;
        }
        asm volatile("cp.async.wait_group 1;\n" ::: "memory");
        __syncthreads();
        if (t + 2 < T) load_stage((t + 2) % NSTB, t + 2);
        else asm volatile("cp.async.commit_group;\n");

        if ((t & 1) == 0) {
            int iu = u & 127;
#pragma unroll
            for (int t4 = 0; t4 < 4; t4++) {
                __half ph = *(const __half*)(smem + SM_P + (m_base + gq + 8 * t4) * 264 + iu * 2);
                pb[t4] = __half2half2(ph);
            }
        }
        const char* bst = smem + SM_B + (t % NSTB) * BSTG;

#pragma unroll
        for (int ss = 0; ss < 4; ss++) {
            int jb = (t & 1) * 64 + ss * 16;
            // A fragments (K-only -> same for both N-halves)
            uint32_t afr[2][4];
#pragma unroll
            for (int mt = 0; mt < 2; mt++) {
                const char* r0p = smem + SM_S + (m_base + mt * 16 + gq) * 272 + jb * 2 + s_cb;
                const char* r1p = r0p + 8 * 272;
                __half2 s00 = *(const __half2*)(r0p);
                __half2 s10 = *(const __half2*)(r1p);
                __half2 s01 = *(const __half2*)(r0p + 16);
                __half2 s11 = *(const __half2*)(r1p + 16);
                __half2 a0 = __hmul2(pb[mt * 2],     s00);
                __half2 a1 = __hmul2(pb[mt * 2 + 1], s10);
                __half2 a2 = __hmul2(pb[mt * 2],     s01);
                __half2 a3 = __hmul2(pb[mt * 2 + 1], s11);
                afr[mt][0] = *(uint32_t*)&a0; afr[mt][1] = *(uint32_t*)&a1;
                afr[mt][2] = *(uint32_t*)&a2; afr[mt][3] = *(uint32_t*)&a3;
            }

#define MMA_TILE(jj, tl)                                                        \
            {                                                                   \
                const char* brow = bst + ((tl) * 8 + gq) * BROW + ss * 32 + l4 * 4; \
                uint32_t b0 = *(const uint32_t*)(brow);                         \
                uint32_t b1 = *(const uint32_t*)(brow + 16);                    \
                _Pragma("unroll")                                               \
                for (int mt = 0; mt < 2; mt++) {                                \
                    asm volatile(                                               \
                        "mma.sync.aligned.m16n8k16.row.col.f32.f16.f16.f32 "    \
                        "{%0,%1,%2,%3}, {%4,%5,%6,%7}, {%8,%9}, {%0,%1,%2,%3};" \
                        : "+f"(acc[mt][jj][0]), "+f"(acc[mt][jj][1]),           \
                          "+f"(acc[mt][jj][2]), "+f"(acc[mt][jj][3])            \
                        : "r"(afr[mt][0]), "r"(afr[mt][1]),                     \
                          "r"(afr[mt][2]), "r"(afr[mt][3]),                     \
                          "r"(b0), "r"(b1));                                    \
                }                                                               \
            }

            if (wn == 0) {
#pragma unroll
                for (int j = 0; j < 7; j++) MMA_TILE(j, j)
            } else {
#pragma unroll
                for (int j = 0; j < 5; j++) MMA_TILE(j, 7 + j)
                if (h == 0) MMA_TILE(5, 12)
            }
#undef MMA_TILE
        }
    }

    flush(m);
}

// ---------------- epilogue: sum 4 partial slots, bias+relu, @W2 ----------------
__global__ void k_final(const float* __restrict__ b1, const float* __restrict__ W2,
                        const float* __restrict__ b2, float* __restrict__ out) {
    int g = (blockIdx.x * blockDim.x + threadIdx.x) >> 5;
    int lane = threadIdx.x & 31;
    if (g >= GG) return;
    float a0 = 0.f, a1 = 0.f;
    for (int n = lane; n < NOUT; n += 32) {
        float v = b1[n];
#pragma unroll
        for (int zz = 0; zz < NSLOTS_ZP; zz++) v += d_Zp[((size_t)zz * GG + g) * 208 + n];
        v = fmaxf(v, 0.f);
        a0 += v * W2[n * 2];
        a1 += v * W2[n * 2 + 1];
    }
#pragma unroll
    for (int o = 16; o; o >>= 1) {
        a0 += __shfl_down_sync(0xffffffffu, a0, o);
        a1 += __shfl_down_sync(0xffffffffu, a1, o);
    }
    if (lane == 0) { out[g * 2] = a0 + b2[0]; out[g * 2 + 1] = a1 + b2[1]; }
}

// ---------------- host ----------------
extern "C" void kernel_launch(void* const* d_in, const int* in_sizes, int n_in,
                              void* d_out, int out_size) {
    const float* x       = (const float*)d_in[0];
    const int*   ei      = (const int*)d_in[1];
    const int*   set_idx = (const int*)d_in[2];
    const float* ir      = (const float*)d_in[4];
    const float* Wl      = (const float*)d_in[5];
    const float* bl      = (const float*)d_in[6];
    const float* Wr      = (const float*)d_in[7];
    const float* Wir     = (const float*)d_in[8];
    const float* bir     = (const float*)d_in[9];
    const float* W1      = (const float*)d_in[10];
    const float* b1      = (const float*)d_in[11];
    const float* W2      = (const float*)d_in[12];
    const float* b2      = (const float*)d_in[13];
    float* out = (float*)d_out;

    // one-time host-side setup (streams/events are host resources, no dev mem)
    static cudaStream_t s1 = nullptr, s2 = nullptr;
    static cudaEvent_t ef = nullptr, e1 = nullptr, e2 = nullptr;
    static int nsm = 0;
    if (!s1) {
        cudaStreamCreateWithFlags(&s1, cudaStreamNonBlocking);
        cudaStreamCreateWithFlags(&s2, cudaStreamNonBlocking);
        cudaEventCreateWithFlags(&ef, cudaEventDisableTiming);
        cudaEventCreateWithFlags(&e1, cudaEventDisableTiming);
        cudaEventCreateWithFlags(&e2, cudaEventDisableTiming);
        cudaFuncSetAttribute(k_decode, cudaFuncAttributeMaxDynamicSharedMemorySize, SM_TOTAL);
        cudaDeviceGetAttribute(&nsm, cudaDevAttrMultiProcessorCount, 0);
        if (nsm < 4) nsm = 4;
    }

    void *p_meta, *p_zp;
    cudaGetSymbolAddress(&p_meta, d_meta);
    cudaGetSymbolAddress(&p_zp,   d_Zp);
    // single zero-memset covers mark (0 = unmarked), bits, cnt
    cudaMemsetAsync(p_meta, 0, (size_t)(NN + NN / 32 + NSLOT) * 4, 0);

    // fork: independent stages on side streams
    cudaEventRecord(ef, 0);
    cudaStreamWaitEvent(s1, ef, 0);
    cudaStreamWaitEvent(s2, ef, 0);
    cudaMemsetAsync(p_zp, 0, (size_t)NSLOTS_ZP * GG * 208 * 4, s1);
    k_prep<<<dim3(512, 7), dim3(32, 8), 0, s1>>>(W1);
    k_sgemm<<<GG / 64, 256, 0, s2>>>(ir, Wir, bir);

    // main chain on origin stream
    k_mark<<<NSLOT / 256, 256>>>(set_idx);
    k_fill<<<EE / 2048, 256>>>(ei);
    k_agg<<<NSLOT / 8, 256>>>(x);
    k_hgemm<<<NSLOT / 128, 256>>>(Wl, Wr, bl);

    // join
    cudaEventRecord(e1, s1);
    cudaEventRecord(e2, s2);
    cudaStreamWaitEvent(0, e1, 0);
    cudaStreamWaitEvent(0, e2, 0);

    k_decode<<<2 * nsm, 256, SM_TOTAL>>>();
    k_final<<<(GG * 32 + 255) / 256, 256>>>(b1, W2, b2, out);
}

// round 17
// speedup vs baseline: 1.1356x; 1.0077x over previous
#include <cuda_runtime.h>
#include <cuda_fp16.h>
#include <cstdint>

// ---------------- problem constants (fixed shapes) ----------------
#define NN     131072      // nodes
#define EE     2097152     // edges
#define GG     8192        // graphs
#define NPG    16
#define NSLOT  16384       // 2 per graph
#define GS     64
#define NOUT   200
#define NSLOTS_ZP 4        // partial slots for decode
#define ECAP   64          // per-slot edge bucket capacity
#define NUNITS 8192        // 64 M-blocks x 128 K-chunks

// ---------------- scratch (device globals; no runtime alloc) ----------------
// d_meta = [mark(NN) | bits(NN/32) | cnt(NSLOT)], single zero-memset.
// mark encoding: 0 = unmarked, slot+1 = marked.
__device__ int      d_meta[NN + NN / 32 + NSLOT];
#define D_MARK (d_meta)
#define D_BITS ((uint32_t*)(d_meta + NN))
#define D_CNT  (d_meta + NN + NN / 32)

__device__ int      d_node_of[NSLOT];
__device__ int      d_elist[NSLOT * ECAP];    // [slot][ECAP]
__device__ float    d_MX[NSLOT * 256];        // [slot][mean(128) | xv(128)]
__device__ __half   d_Hh[NSLOT * GS];         // h per slot (fp16)
__device__ __half   d_Sh[GG * 128];           // fused ir features (fp16)
__device__ __half   d_W1h[208 * 16384];       // W1 transposed (n-major), fp16, zero-padded
__device__ float    d_Zp[(size_t)NSLOTS_ZP * GG * 208]; // decode partials (4 slots)

__device__ __forceinline__ uint32_t su32(const void* p) {
    return (uint32_t)__cvta_generic_to_shared(p);
}

// ---------------- stage 0: W1 transpose + fp16 round ----------------
__global__ void k_prep(const float* __restrict__ W1) {
    __shared__ float tile[32][33];
    int kb = blockIdx.x * 32, nb = blockIdx.y * 32;
    int tx = threadIdx.x, ty = threadIdx.y;
#pragma unroll
    for (int r = 0; r < 4; r++) {
        int k = kb + ty + r * 8;
        int n = nb + tx;
        tile[ty + r * 8][tx] = (n < NOUT) ? W1[(size_t)k * NOUT + n] : 0.f;
    }
    __syncthreads();
#pragma unroll
    for (int r = 0; r < 4; r++) {
        int n = nb + ty + r * 8;
        if (n < 208) d_W1h[(size_t)n * 16384 + kb + tx] = __float2half_rn(tile[tx][ty + r * 8]);
    }
}

// ---------------- stage A: mark / bucket-fill / aggregate ----------------
__global__ void k_mark(const int* __restrict__ set_idx) {
    int s = blockIdx.x * blockDim.x + threadIdx.x;
    if (s >= NSLOT) return;
    int g = s >> 1, k = s & 1;
    int v = g * NPG + set_idx[g * 2 + k];
    d_node_of[s] = v;
    atomicMax(&D_MARK[v], s + 1);
    atomicOr(&D_BITS[v >> 5], 1u << (v & 31));
}

// bucketed edge fill; 8 edges/thread; bitmask pre-filter; batched mark loads
__global__ void k_fill(const int* __restrict__ ei) {
    int e0 = (blockIdx.x * blockDim.x + threadIdx.x) * 8;
    if (e0 >= EE) return;
    int4 a = *(const int4*)&ei[EE + e0];
    int4 b = *(const int4*)&ei[EE + e0 + 4];
    int v[8] = {a.x, a.y, a.z, a.w, b.x, b.y, b.z, b.w};
    uint32_t hit = 0;
#pragma unroll
    for (int q = 0; q < 8; q++)
        hit |= ((D_BITS[v[q] >> 5] >> (v[q] & 31)) & 1u) << q;
    if (!hit) return;
    // phase 2: batched mark loads (MLP across all hits)
    int r[8];
#pragma unroll
    for (int q = 0; q < 8; q++)
        if (hit & (1u << q)) r[q] = D_MARK[v[q]] - 1;
    // phase 3: atomics + stores
#pragma unroll
    for (int q = 0; q < 8; q++) {
        if (hit & (1u << q)) {
            int p = atomicAdd(&D_CNT[r[q]], 1);
            if (p < ECAP) d_elist[r[q] * ECAP + p] = ei[e0 + q];
        }
    }
}

// aggregate: every slot reads its representative's bucket; MLP-8 gather
__global__ void k_agg(const float* __restrict__ x) {
    int s = blockIdx.x * 8 + (threadIdx.x >> 5);
    int lane = threadIdx.x & 31;
    int v = d_node_of[s];
    int rep = D_MARK[v] - 1;                     // bucket key (== s unless dup)
    const float4* x4 = (const float4*)x;
    const int* el = &d_elist[rep * ECAP];
    int deg = D_CNT[rep];
    int n = deg > ECAP ? ECAP : deg;
    float4 acc = make_float4(0.f, 0.f, 0.f, 0.f);
    int i = 0;
    for (; i + 8 <= n; i += 8) {
        float4 t[8];
#pragma unroll
        for (int q = 0; q < 8; q++) t[q] = x4[(size_t)el[i + q] * 32 + lane];
        acc.x += ((t[0].x + t[1].x) + (t[2].x + t[3].x)) + ((t[4].x + t[5].x) + (t[6].x + t[7].x));
        acc.y += ((t[0].y + t[1].y) + (t[2].y + t[3].y)) + ((t[4].y + t[5].y) + (t[6].y + t[7].y));
        acc.z += ((t[0].z + t[1].z) + (t[2].z + t[3].z)) + ((t[4].z + t[5].z) + (t[6].z + t[7].z));
        acc.w += ((t[0].w + t[1].w) + (t[2].w + t[3].w)) + ((t[4].w + t[5].w) + (t[6].w + t[7].w));
    }
    for (; i + 2 <= n; i += 2) {
        float4 t0 = x4[(size_t)el[i] * 32 + lane];
        float4 t1 = x4[(size_t)el[i + 1] * 32 + lane];
        acc.x += t0.x + t1.x; acc.y += t0.y + t1.y;
        acc.z += t0.z + t1.z; acc.w += t0.w + t1.w;
    }
    if (i < n) {
        float4 t = x4[(size_t)el[i] * 32 + lane];
        acc.x += t.x; acc.y += t.y; acc.z += t.z; acc.w += t.w;
    }
    float inv = 1.f / (float)(deg > 0 ? deg : 1);
    acc.x *= inv; acc.y *= inv; acc.z *= inv; acc.w *= inv;
    float4* MX4 = (float4*)d_MX;
    MX4[(size_t)s * 64 + lane]      = acc;
    MX4[(size_t)s * 64 + 32 + lane] = x4[(size_t)v * 32 + lane];
}

// ---------------- stage B: H = relu(MX @ [Wl;Wr] + bl) -> fp16 ----------------
__global__ void k_hgemm(const float* __restrict__ Wl, const float* __restrict__ Wr,
                        const float* __restrict__ bl) {
    __shared__ float As[16][132];   // [k][row], transposed
    __shared__ float Bs[16][64];
    int tid = threadIdx.x;
    int tx = tid & 15, ty = tid >> 4;
    int row0 = blockIdx.x * 128;
    float acc[8][4];
#pragma unroll
    for (int i = 0; i < 8; i++)
#pragma unroll
        for (int j = 0; j < 4; j++) acc[i][j] = 0.f;

    for (int kb = 0; kb < 256; kb += 16) {
        for (int l = tid; l < 512; l += 256) {
            int r = l >> 2, q = l & 3;
            float4 v = *(const float4*)&d_MX[(size_t)(row0 + r) * 256 + kb + q * 4];
            As[q * 4 + 0][r] = v.x; As[q * 4 + 1][r] = v.y;
            As[q * 4 + 2][r] = v.z; As[q * 4 + 3][r] = v.w;
        }
        {
            int k = tid >> 4, o4 = (tid & 15) * 4;
            int kg = kb + k;
            const float* Wsrc = (kg < 128) ? &Wl[kg * 64 + o4] : &Wr[(kg - 128) * 64 + o4];
            *(float4*)&Bs[k][o4] = *(const float4*)Wsrc;
        }
        __syncthreads();
#pragma unroll
        for (int k = 0; k < 16; k++) {
            float a[8], b[4];
#pragma unroll
            for (int i = 0; i < 8; i++) a[i] = As[k][ty * 8 + i];
#pragma unroll
            for (int j = 0; j < 4; j++) b[j] = Bs[k][tx * 4 + j];
#pragma unroll
            for (int i = 0; i < 8; i++)
#pragma unroll
                for (int j = 0; j < 4; j++) acc[i][j] += a[i] * b[j];
        }
        __syncthreads();
    }
#pragma unroll
    for (int i = 0; i < 8; i++)
#pragma unroll
        for (int j = 0; j < 4; j++) {
            int o = tx * 4 + j;
            d_Hh[(size_t)(row0 + ty * 8 + i) * 64 + o] =
                __float2half_rn(fmaxf(acc[i][j] + bl[o], 0.f));
        }
}

// ---------------- stage C: S = relu(ir @ Wir + bir) -> fp16 ----------------
__global__ void k_sgemm(const float* __restrict__ ir, const float* __restrict__ Wir,
                        const float* __restrict__ bir) {
    __shared__ float irs[64][32];
    __shared__ float Ws[32][128];
    int tid = threadIdx.x;
    int g0 = blockIdx.x * 64;
    for (int l = tid; l < 64 * 32; l += 256) irs[l >> 5][l & 31] = ir[(size_t)g0 * 32 + l];
    for (int l = tid; l < 32 * 128; l += 256) Ws[l >> 7][l & 127] = Wir[l];
    __syncthreads();
    int o = tid & 127, h = tid >> 7;
    float bo = bir[o];
    for (int gg = h; gg < 64; gg += 2) {
        float acc = bo;
#pragma unroll
        for (int k = 0; k < 32; k++) acc += irs[gg][k] * Ws[k][o];
        d_Sh[(size_t)(g0 + gg) * 128 + o] = __float2half_rn(fmaxf(acc, 0.f));
    }
}

// ---------------- stage D: persistent decode GEMM, 2 CTAs/SM, k64 stages ------
// Z[8192,200] = A[8192,16384] @ W1, A[g, i*128+j] = P[g,i]*S[g,j].
// Grid = 2*NSM. CTA c: h = c&1 selects N-half, c2 = c>>1 selects unit range.
// Stage = k64 (four k16 sub-steps per sync), 3-deep cp.async ring.
#define NSTB 3
#define BROW 144                       // 128B data + 16B pad (bank = 4*gq+l4, distinct)
#define BSTG (104 * BROW)              // 14976 B per stage
#define SM_B 0
#define SM_S (NSTB * BSTG)             // 44928; S: 128 rows x 272B = 34816
#define SM_P (SM_S + 128 * 272)        // 79744; P: 128 rows x 264B = 33792
#define SM_TOTAL (SM_P + 128 * 264)    // 113536

__global__ void __launch_bounds__(256, 2)
k_decode() {
    extern __shared__ char smem[];
    uint32_t sb = su32(smem);
    int tid = threadIdx.x;
    int lane = tid & 31, warp = tid >> 5;
    int wm = warp & 3, wn = warp >> 2;
    int gq = lane >> 2, l4 = lane & 3;
    int m_base = wm * 32;
    int c = blockIdx.x;
    int h = c & 1, c2 = c >> 1, NC2 = gridDim.x >> 1;
    int u0 = (c2 * NUNITS) / NC2;
    int u1 = ((c2 + 1) * NUNITS) / NC2;
    int T = (u1 - u0) * 2;             // k64 stages (2 per K-chunk of 128)
    int m = u0 >> 7;

    // ---- tile loaders
    auto load_tiles = [&](int mb) {
        int g0 = mb * 128;
        for (int l = tid; l < 2048; l += 256) {
            int row = l >> 4, cc = l & 15;
            *(float4*)(smem + SM_S + row * 272 + cc * 16) =
                *(const float4*)((const char*)d_Sh + (size_t)(g0 + row) * 256 + cc * 16);
        }
        for (int l = tid; l < 4096; l += 256) {
            int row = l >> 5, grp = l & 31;
            *(float2*)(smem + SM_P + row * 264 + grp * 8) =
                *(const float2*)((const char*)d_Hh +
                    ((size_t)(2 * (g0 + row) + (grp >> 4)) * 64 + (grp & 15) * 4) * 2);
        }
    };
    // ---- B stage loader (cp.async): 104 rows x 128B (k64)
    auto load_stage = [&](int buf, int t) {
        int iu = (u0 + (t >> 1)) & 127;
        int kb = iu * 128 + (t & 1) * 64;
        for (int l = tid; l < 832; l += 256) {
            int row = l >> 3, q = l & 7;
            uint32_t dst = sb + SM_B + buf * BSTG + row * BROW + q * 16;
            const char* src = (const char*)(d_W1h + (size_t)(h * 104 + row) * 16384 + kb + q * 8);
            asm volatile("cp.async.cg.shared.global [%0], [%1], 16;\n"
                         :: "r"(dst), "l"(src));
        }
        asm volatile("cp.async.commit_group;\n");
    };

    float acc[2][7][4];
#pragma unroll
    for (int a = 0; a < 2; a++)
#pragma unroll
        for (int b = 0; b < 7; b++)
#pragma unroll
            for (int q = 0; q < 4; q++) acc[a][b][q] = 0.f;

    auto flush = [&](int mb) {
        int slot = c2 & 3;
        int base_col = h * 104;
#pragma unroll
        for (int mt = 0; mt < 2; mt++) {
            int gr = mb * 128 + m_base + mt * 16 + gq;
            size_t b0 = ((size_t)slot * GG + gr) * 208;
            size_t b1 = ((size_t)slot * GG + gr + 8) * 208;
            if (wn == 0) {
#pragma unroll
                for (int j = 0; j < 7; j++) {
                    int c0 = base_col + j * 8 + 2 * l4;
                    *(float2*)&d_Zp[b0 + c0] = make_float2(acc[mt][j][0], acc[mt][j][1]);
                    *(float2*)&d_Zp[b1 + c0] = make_float2(acc[mt][j][2], acc[mt][j][3]);
                }
            } else {
#pragma unroll
                for (int j = 0; j < 5; j++) {
                    int c0 = base_col + 56 + j * 8 + 2 * l4;
                    *(float2*)&d_Zp[b0 + c0] = make_float2(acc[mt][j][0], acc[mt][j][1]);
                    *(float2*)&d_Zp[b1 + c0] = make_float2(acc[mt][j][2], acc[mt][j][3]);
                }
                if (h == 0) {
                    int c0 = 96 + 2 * l4;
                    *(float2*)&d_Zp[b0 + c0] = make_float2(acc[mt][5][0], acc[mt][5][1]);
                    *(float2*)&d_Zp[b1 + c0] = make_float2(acc[mt][5][2], acc[mt][5][3]);
                }
            }
        }
#pragma unroll
        for (int a = 0; a < 2; a++)
#pragma unroll
            for (int b = 0; b < 7; b++)
#pragma unroll
                for (int q = 0; q < 4; q++) acc[a][b][q] = 0.f;
    };

    load_tiles(m);
    __syncthreads();
    load_stage(0, 0); load_stage(1, 1);

    __half2 pb[4];
    const int s_cb = (2 * l4) * 2;       // byte offset of j0 within S row

    for (int t = 0; t < T; t++) {
        int u = u0 + (t >> 1);
        int mblk = u >> 7;
        if (mblk != m) {
            flush(m);
            __syncthreads();
            load_tiles(mblk);
            __syncthreads();
            m = mblk;
        }
        asm volatile("cp.async.wait_group 1;\n" ::: "memory");
        __syncthreads();
        if (t + 2 < T) load_stage((t + 2) % NSTB, t + 2);
        else asm volatile("cp.async.commit_group;\n");

        if ((t & 1) == 0) {
            int iu = u & 127;
#pragma unroll
            for (int t4 = 0; t4 < 4; t4++) {
                __half ph = *(const __half*)(smem + SM_P + (m_base + gq + 8 * t4) * 264 + iu * 2);
                pb[t4] = __half2half2(ph);
            }
        }
        const char* bst = smem + SM_B + (t % NSTB) * BSTG;

#pragma unroll
        for (int ss = 0; ss < 4; ss++) {
            int jb = (t & 1) * 64 + ss * 16;
            // A fragments (K-only -> same for both N-halves)
            uint32_t afr[2][4];
#pragma unroll
            for (int mt = 0; mt < 2; mt++) {
                const char* r0p = smem + SM_S + (m_base + mt * 16 + gq) * 272 + jb * 2 + s_cb;
                const char* r1p = r0p + 8 * 272;
                __half2 s00 = *(const __half2*)(r0p);
                __half2 s10 = *(const __half2*)(r1p);
                __half2 s01 = *(const __half2*)(r0p + 16);
                __half2 s11 = *(const __half2*)(r1p + 16);
                __half2 a0 = __hmul2(pb[mt * 2],     s00);
                __half2 a1 = __hmul2(pb[mt * 2 + 1], s10);
                __half2 a2 = __hmul2(pb[mt * 2],     s01);
                __half2 a3 = __hmul2(pb[mt * 2 + 1], s11);
                afr[mt][0] = *(uint32_t*)&a0; afr[mt][1] = *(uint32_t*)&a1;
                afr[mt][2] = *(uint32_t*)&a2; afr[mt][3] = *(uint32_t*)&a3;
            }

#define MMA_TILE(jj, tl)                                                        \
            {                                                                   \
                const char* brow = bst + ((tl) * 8 + gq) * BROW + ss * 32 + l4 * 4; \
                uint32_t b0 = *(const uint32_t*)(brow);                         \
                uint32_t b1 = *(const uint32_t*)(brow + 16);                    \
                _Pragma("unroll")                                               \
                for (int mt = 0; mt < 2; mt++) {                                \
                    asm volatile(                                               \
                        "mma.sync.aligned.m16n8k16.row.col.f32.f16.f16.f32 "    \
                        "{%0,%1,%2,%3}, {%4,%5,%6,%7}, {%8,%9}, {%0,%1,%2,%3};" \
                        : "+f"(acc[mt][jj][0]), "+f"(acc[mt][jj][1]),           \
                          "+f"(acc[mt][jj][2]), "+f"(acc[mt][jj][3])            \
                        : "r"(afr[mt][0]), "r"(afr[mt][1]),                     \
                          "r"(afr[mt][2]), "r"(afr[mt][3]),                     \
                          "r"(b0), "r"(b1));                                    \
                }                                                               \
            }

            if (wn == 0) {
#pragma unroll
                for (int j = 0; j < 7; j++) MMA_TILE(j, j)
            } else {
#pragma unroll
                for (int j = 0; j < 5; j++) MMA_TILE(j, 7 + j)
                if (h == 0) MMA_TILE(5, 12)
            }
#undef MMA_TILE
        }
    }

    flush(m);
}

// ---------------- epilogue: sum 4 partial slots, bias+relu, @W2 ----------------
__global__ void k_final(const float* __restrict__ b1, const float* __restrict__ W2,
                        const float* __restrict__ b2, float* __restrict__ out) {
    int g = (blockIdx.x * blockDim.x + threadIdx.x) >> 5;
    int lane = threadIdx.x & 31;
    if (g >= GG) return;
    float a0 = 0.f, a1 = 0.f;
    for (int n = lane; n < NOUT; n += 32) {
        float v = b1[n];
#pragma unroll
        for (int zz = 0; zz < NSLOTS_ZP; zz++) v += d_Zp[((size_t)zz * GG + g) * 208 + n];
        v = fmaxf(v, 0.f);
        a0 += v * W2[n * 2];
        a1 += v * W2[n * 2 + 1];
    }
#pragma unroll
    for (int o = 16; o; o >>= 1) {
        a0 += __shfl_down_sync(0xffffffffu, a0, o);
        a1 += __shfl_down_sync(0xffffffffu, a1, o);
    }
    if (lane == 0) { out[g * 2] = a0 + b2[0]; out[g * 2 + 1] = a1 + b2[1]; }
}

// ---------------- host ----------------
extern "C" void kernel_launch(void* const* d_in, const int* in_sizes, int n_in,
                              void* d_out, int out_size) {
    const float* x       = (const float*)d_in[0];
    const int*   ei      = (const int*)d_in[1];
    const int*   set_idx = (const int*)d_in[2];
    const float* ir      = (const float*)d_in[4];
    const float* Wl      = (const float*)d_in[5];
    const float* bl      = (const float*)d_in[6];
    const float* Wr      = (const float*)d_in[7];
    const float* Wir     = (const float*)d_in[8];
    const float* bir     = (const float*)d_in[9];
    const float* W1      = (const float*)d_in[10];
    const float* b1      = (const float*)d_in[11];
    const float* W2      = (const float*)d_in[12];
    const float* b2      = (const float*)d_in[13];
    float* out = (float*)d_out;

    // one-time host-side setup (streams/events are host resources, no dev mem)
    static cudaStream_t s1 = nullptr, s2 = nullptr;
    static cudaEvent_t ef = nullptr, e1 = nullptr, e2 = nullptr;
    static int nsm = 0;
    if (!s1) {
        cudaStreamCreateWithFlags(&s1, cudaStreamNonBlocking);
        cudaStreamCreateWithFlags(&s2, cudaStreamNonBlocking);
        cudaEventCreateWithFlags(&ef, cudaEventDisableTiming);
        cudaEventCreateWithFlags(&e1, cudaEventDisableTiming);
        cudaEventCreateWithFlags(&e2, cudaEventDisableTiming);
        cudaFuncSetAttribute(k_decode, cudaFuncAttributeMaxDynamicSharedMemorySize, SM_TOTAL);
        cudaDeviceGetAttribute(&nsm, cudaDevAttrMultiProcessorCount, 0);
        if (nsm < 4) nsm = 4;
    }

    void *p_meta, *p_zp;
    cudaGetSymbolAddress(&p_meta, d_meta);
    cudaGetSymbolAddress(&p_zp,   d_Zp);
    // single zero-memset covers mark (0 = unmarked), bits, cnt
    cudaMemsetAsync(p_meta, 0, (size_t)(NN + NN / 32 + NSLOT) * 4, 0);

    // fork: independent stages on side streams
    cudaEventRecord(ef, 0);
    cudaStreamWaitEvent(s1, ef, 0);
    cudaStreamWaitEvent(s2, ef, 0);
    cudaMemsetAsync(p_zp, 0, (size_t)NSLOTS_ZP * GG * 208 * 4, s1);
    k_prep<<<dim3(512, 7), dim3(32, 8), 0, s1>>>(W1);
    k_sgemm<<<GG / 64, 256, 0, s2>>>(ir, Wir, bir);

    // main chain on origin stream
    k_mark<<<NSLOT / 256, 256>>>(set_idx);
    k_fill<<<EE / 2048, 256>>>(ei);
    k_agg<<<NSLOT / 8, 256>>>(x);
    k_hgemm<<<NSLOT / 128, 256>>>(Wl, Wr, bl);

    // join
    cudaEventRecord(e1, s1);
    cudaEventRecord(e2, s2);
    cudaStreamWaitEvent(0, e1, 0);
    cudaStreamWaitEvent(0, e2, 0);

    k_decode<<<2 * nsm, 256, SM_TOTAL>>>();
    k_final<<<(GG * 32 + 255) / 256, 256>>>(b1, W2, b2, out);
}